// round 5
// baseline (speedup 1.0000x reference)
#include <cuda_runtime.h>
#include <cuda_bf16.h>
#include <cstdint>

#define BB 2
#define SS 2048
#define DD 512
#define HH 8
#define LR 7
#define MTOT (BB*SS)        // 4096
#define K3 (3*DD)           // 1536

// scratch
__device__ float g_q[MTOT * DD];
__device__ float g_k[MTOT * DD];
__device__ float g_w[MTOT * 128];           // [b*S+i][h*16+jj] normalized band weights
__device__ __nv_bfloat16 g_a3[MTOT * K3];   // [hi | lo | hi] along K
__device__ __nv_bfloat16 g_b3q[DD * K3];    // [hi | hi | lo] along K, rows = n
__device__ __nv_bfloat16 g_b3k[DD * K3];

#define SWZ128(off) ((off) ^ (((off) >> 3) & 0x70))

__device__ __forceinline__ uint32_t smem_u32(const void* p) {
    uint32_t a;
    asm("{ .reg .u64 t; cvta.to.shared.u64 t, %1; cvt.u32.u64 %0, t; }" : "=r"(a) : "l"(p));
    return a;
}
__device__ __forceinline__ void cp16(uint32_t s, const void* g) {
    asm volatile("cp.async.cg.shared.global [%0], [%1], 16;" :: "r"(s), "l"(g));
}
#define CP_COMMIT() asm volatile("cp.async.commit_group;" ::: "memory")

__device__ __forceinline__ void ldm_x4(uint32_t& r0, uint32_t& r1, uint32_t& r2, uint32_t& r3, uint32_t a) {
    asm volatile("ldmatrix.sync.aligned.m8n8.x4.shared.b16 {%0,%1,%2,%3}, [%4];"
                 : "=r"(r0), "=r"(r1), "=r"(r2), "=r"(r3) : "r"(a));
}
__device__ __forceinline__ void ldm_x2(uint32_t& r0, uint32_t& r1, uint32_t a) {
    asm volatile("ldmatrix.sync.aligned.m8n8.x2.shared.b16 {%0,%1}, [%2];"
                 : "=r"(r0), "=r"(r1) : "r"(a));
}
__device__ __forceinline__ void mma16816(float* d, const uint32_t* a, const uint32_t* b) {
    asm volatile("mma.sync.aligned.m16n8k16.row.col.f32.bf16.bf16.f32 "
                 "{%0,%1,%2,%3}, {%4,%5,%6,%7}, {%8,%9}, {%0,%1,%2,%3};"
                 : "+f"(d[0]), "+f"(d[1]), "+f"(d[2]), "+f"(d[3])
                 : "r"(a[0]), "r"(a[1]), "r"(a[2]), "r"(a[3]), "r"(b[0]), "r"(b[1]));
}

// ---------------------------------------------------------------------------
// split hidden_states into bf16 hi/lo, tripled K layout [hi|lo|hi]
// ---------------------------------------------------------------------------
__global__ void split_hs(const float* __restrict__ hs) {
    int idx = blockIdx.x * 256 + threadIdx.x;     // float4 index
    int m = idx >> 7;
    int c = idx & 127;
    float4 v = ((const float4*)hs)[idx];
    __nv_bfloat16 hx = __float2bfloat16(v.x), hy = __float2bfloat16(v.y);
    __nv_bfloat16 hz = __float2bfloat16(v.z), hw = __float2bfloat16(v.w);
    __nv_bfloat16 lx = __float2bfloat16(v.x - __bfloat162float(hx));
    __nv_bfloat16 ly = __float2bfloat16(v.y - __bfloat162float(hy));
    __nv_bfloat16 lz = __float2bfloat16(v.z - __bfloat162float(hz));
    __nv_bfloat16 lw = __float2bfloat16(v.w - __bfloat162float(hw));
    __nv_bfloat162 H0; H0.x = hx; H0.y = hy;
    __nv_bfloat162 H1; H1.x = hz; H1.y = hw;
    __nv_bfloat162 L0; L0.x = lx; L0.y = ly;
    __nv_bfloat162 L1; L1.x = lz; L1.y = lw;
    __nv_bfloat16* p = g_a3 + (size_t)m * K3 + 4 * c;
    *(__nv_bfloat162*)(p)          = H0; *(__nv_bfloat162*)(p + 2)          = H1;
    *(__nv_bfloat162*)(p + DD)     = L0; *(__nv_bfloat162*)(p + DD + 2)     = L1;
    *(__nv_bfloat162*)(p + 2*DD)   = H0; *(__nv_bfloat162*)(p + 2*DD + 2)   = H1;
}

// ---------------------------------------------------------------------------
// split + transpose W (stored [k, n]) into B3 [n, 3K] = [hi|hi|lo]
// ---------------------------------------------------------------------------
__global__ void split_w(const float* __restrict__ Wq, const float* __restrict__ Wk) {
    __shared__ float t[32][33];
    const float* W = blockIdx.z ? Wk : Wq;
    __nv_bfloat16* B3 = blockIdx.z ? g_b3k : g_b3q;
    int n0 = blockIdx.x * 32, k0 = blockIdx.y * 32;
    int tx = threadIdx.x, ty = threadIdx.y;           // (32, 8)
#pragma unroll
    for (int r = 0; r < 4; r++)
        t[ty + r * 8][tx] = W[(size_t)(k0 + ty + r * 8) * DD + n0 + tx];
    __syncthreads();
#pragma unroll
    for (int r = 0; r < 4; r++) {
        int n = n0 + ty + r * 8, k = k0 + tx;
        float v = t[tx][ty + r * 8];
        __nv_bfloat16 h = __float2bfloat16(v);
        __nv_bfloat16 l = __float2bfloat16(v - __bfloat162float(h));
        B3[(size_t)n * K3 + k]        = h;
        B3[(size_t)n * K3 + DD + k]   = h;
        B3[(size_t)n * K3 + 2*DD + k] = l;
    }
}

// ---------------------------------------------------------------------------
// mma.sync bf16 GEMM: C[4096,512] = A3[4096,1536] * B3[512,1536]^T, f32 acc
// ---------------------------------------------------------------------------
#define MT 128
#define NT 128
#define KT 64
#define NK 24          // 1536/64
#define STG 32768u     // 16KB A + 16KB B
#define NSTG 3
#define GEMM_SMEM (NSTG * STG)

__device__ __forceinline__ void load_tile(int tile, int stg,
                                          const char* Ab, const char* Bb,
                                          uint32_t sb, int tid) {
    size_t koff = (size_t)tile * (KT * 2);
    uint32_t sA = sb + (uint32_t)stg * STG;
    uint32_t sB = sA + 16384u;
#pragma unroll
    for (int c = 0; c < 4; c++) {
        int q = tid + c * 256;
        int r = q >> 3, col = (q & 7) * 16;
        cp16(sA + SWZ128(r * 128 + col), Ab + (size_t)r * (K3 * 2) + koff + col);
    }
#pragma unroll
    for (int c = 0; c < 4; c++) {
        int q = tid + c * 256;
        int r = q >> 3, col = (q & 7) * 16;
        cp16(sB + SWZ128(r * 128 + col), Bb + (size_t)r * (K3 * 2) + koff + col);
    }
}

__global__ __launch_bounds__(256, 2)
void gemm3() {
    extern __shared__ char smem[];
    uint32_t sb = smem_u32(smem);
    const int tid = threadIdx.x, wid = tid >> 5, lane = tid & 31;
    const int m0 = blockIdx.x * MT;
    const int n0 = blockIdx.y * NT;
    const __nv_bfloat16* B3 = blockIdx.z ? g_b3k : g_b3q;
    float* C = blockIdx.z ? g_k : g_q;

    const char* Ab = (const char*)g_a3 + (size_t)m0 * (K3 * 2);
    const char* Bb = (const char*)B3 + (size_t)n0 * (K3 * 2);

    const int wm = wid & 1;
    const int wn = wid >> 1;

    float acc[4][4][4];
#pragma unroll
    for (int i = 0; i < 4; i++)
#pragma unroll
        for (int j = 0; j < 4; j++)
#pragma unroll
            for (int r = 0; r < 4; r++) acc[i][j][r] = 0.f;

    load_tile(0, 0, Ab, Bb, sb, tid); CP_COMMIT();
    load_tile(1, 1, Ab, Bb, sb, tid); CP_COMMIT();

    const int a_row = wm * 64 + (lane & 15);
    const int a_cg  = (lane >> 4) * 16;
    const int b_row = wn * 32 + (lane & 7);
    const int b_cg  = ((lane >> 3) & 1) * 16;

    for (int t = 0; t < NK; t++) {
        asm volatile("cp.async.wait_group 1;" ::: "memory");
        __syncthreads();

        if (t + 2 < NK)
            load_tile(t + 2, (t + 2) % NSTG, Ab, Bb, sb, tid);
        CP_COMMIT();

        uint32_t sA = sb + (uint32_t)(t % NSTG) * STG;
        uint32_t sB = sA + 16384u;
#pragma unroll
        for (int ks = 0; ks < 4; ks++) {
            uint32_t af[4][4], bf[4][2];
#pragma unroll
            for (int mi = 0; mi < 4; mi++)
                ldm_x4(af[mi][0], af[mi][1], af[mi][2], af[mi][3],
                       sA + SWZ128((a_row + mi * 16) * 128 + ks * 32 + a_cg));
#pragma unroll
            for (int ni = 0; ni < 4; ni++)
                ldm_x2(bf[ni][0], bf[ni][1],
                       sB + SWZ128((b_row + ni * 8) * 128 + ks * 32 + b_cg));
#pragma unroll
            for (int mi = 0; mi < 4; mi++)
#pragma unroll
                for (int ni = 0; ni < 4; ni++)
                    mma16816(acc[mi][ni], af[mi], bf[ni]);
        }
    }

    const int er = lane >> 2;
    const int ec = (lane & 3) * 2;
#pragma unroll
    for (int mi = 0; mi < 4; mi++) {
        int r0 = m0 + wm * 64 + mi * 16 + er;
#pragma unroll
        for (int ni = 0; ni < 4; ni++) {
            int cc = n0 + wn * 32 + ni * 8 + ec;
            *(float2*)(C + (size_t)r0 * DD + cc) = make_float2(acc[mi][ni][0], acc[mi][ni][1]);
            *(float2*)(C + (size_t)(r0 + 8) * DD + cc) = make_float2(acc[mi][ni][2], acc[mi][ni][3]);
        }
    }
}

// ---------------------------------------------------------------------------
// wts: normalized band-softmax weights -> g_w[b*S+i][h*16+jj]
// grid (2048, 2), 256 thr; warp = head; 2 lanes per jj, 32-dim partial dots
// ---------------------------------------------------------------------------
__global__ __launch_bounds__(256)
void wts() {
    const int i = blockIdx.x, b = blockIdx.y;
    const int wid = threadIdx.x >> 5, lane = threadIdx.x & 31;
    const int jj = lane >> 1, half = lane & 1;

    int j = i - LR + jj;
    bool valid = (jj < 15) && (j >= 0) && (j < SS);
    int jc = j < 0 ? 0 : (j >= SS - 1 ? SS - 1 : j);

    const float4* q4 = (const float4*)(g_q + ((size_t)b * SS + i) * DD + wid * 64 + half * 32);
    const float4* k4 = (const float4*)(g_k + ((size_t)b * SS + jc) * DD + wid * 64 + half * 32);

    float acc = 0.f;
#pragma unroll
    for (int t = 0; t < 8; t++) {
        float4 qv = q4[t], kv = k4[t];
        acc += qv.x * kv.x + qv.y * kv.y + qv.z * kv.z + qv.w * kv.w;
    }
    acc += __shfl_xor_sync(0xffffffffu, acc, 1);   // fold the pair: full 64-dim dot

    float sc = valid ? acc * 0.125f : -1e30f;
    float m = sc;
#pragma unroll
    for (int o = 1; o < 32; o <<= 1)
        m = fmaxf(m, __shfl_xor_sync(0xffffffffu, m, o));
    float e = valid ? __expf(sc - m) : 0.f;
    float s = e;
#pragma unroll
    for (int o = 1; o < 32; o <<= 1)
        s += __shfl_xor_sync(0xffffffffu, s, o);    // counts each jj twice
    float w = e * (2.f / s);

    if (half == 0)
        g_w[(((size_t)b * SS + i) << 7) + wid * 16 + jj] = w;   // jj=15 writes 0
}

// ---------------------------------------------------------------------------
// ctx: out[b,h,i,:] = sum_jj w[b,i,h,jj] * hs[b, i-7+jj, :]
// grid (64, 2, 2) = (ic, dc, b); block 256; chunk 32 rows x 256 cols
// smem: 46 hs rows (47KB) + weights 32x128 (16KB)
// ---------------------------------------------------------------------------
#define CTX_SMEM ((46 * 256 + 32 * 128) * 4)

__global__ __launch_bounds__(256, 3)
void ctx(const float* __restrict__ hs, float* __restrict__ out) {
    extern __shared__ float sm[];
    float* sh = sm;                 // [46][256]
    float* sw = sm + 46 * 256;      // [32][128]

    const int ic = blockIdx.x, dc = blockIdx.y, b = blockIdx.z;
    const int i0 = ic * 32, d0 = dc * 256;
    const int tid = threadIdx.x;

    // stage 46 hs rows (clamped) x 256 cols
    for (int idx = tid; idx < 46 * 64; idx += 256) {
        int r = idx >> 6, c = idx & 63;
        int j = i0 - LR + r;
        j = j < 0 ? 0 : (j >= SS ? SS - 1 : j);
        ((float4*)sh)[idx] = ((const float4*)(hs + ((size_t)b * SS + j) * DD + d0))[c];
    }
    // stage weights: 32 rows x 128 floats contiguous
    {
        const float4* gw4 = (const float4*)(g_w + (((size_t)b * SS + i0) << 7));
        for (int idx = tid; idx < 1024; idx += 256)
            ((float4*)sw)[idx] = gw4[idx];
    }
    __syncthreads();

    const int wid = tid >> 5, lane = tid & 31;
    const float4* sh4 = (const float4*)sh;     // row stride 64

#pragma unroll
    for (int ii = 0; ii < 4; ii++) {
        const int il = ii * 8 + wid;           // local row 0..31
        const int ig = i0 + il;
#pragma unroll
        for (int cp = 0; cp < 2; cp++) {
            const int c4 = lane + 32 * cp;     // float4 column 0..63
            float4 v[15];
#pragma unroll
            for (int t = 0; t < 15; t++)
                v[t] = sh4[(il + t) * 64 + c4];

            const float* wp = &sw[il * 128];
#pragma unroll
            for (int h = 0; h < HH; h++) {
                float4 w0 = *(const float4*)(wp + h * 16);
                float4 w1 = *(const float4*)(wp + h * 16 + 4);
                float4 w2 = *(const float4*)(wp + h * 16 + 8);
                float4 w3 = *(const float4*)(wp + h * 16 + 12);
                float4 a; a.x = a.y = a.z = a.w = 0.f;
                float wv;
#define STEP(W, J) wv = (W); a.x += wv * v[J].x; a.y += wv * v[J].y; a.z += wv * v[J].z; a.w += wv * v[J].w;
                STEP(w0.x, 0)  STEP(w0.y, 1)  STEP(w0.z, 2)  STEP(w0.w, 3)
                STEP(w1.x, 4)  STEP(w1.y, 5)  STEP(w1.z, 6)  STEP(w1.w, 7)
                STEP(w2.x, 8)  STEP(w2.y, 9)  STEP(w2.z, 10) STEP(w2.w, 11)
                STEP(w3.x, 12) STEP(w3.y, 13) STEP(w3.z, 14)
#undef STEP
                *(float4*)(out + (((size_t)b * HH + h) * SS + ig) * DD + d0 + c4 * 4) = a;
            }
        }
    }
}

// ---------------------------------------------------------------------------
extern "C" void kernel_launch(void* const* d_in, const int* in_sizes, int n_in,
                              void* d_out, int out_size) {
    const float* hs = (const float*)d_in[0];
    const float* Wq = (const float*)d_in[1];
    const float* Wk = (const float*)d_in[2];
    float* out = (float*)d_out;

    cudaFuncSetAttribute(gemm3, cudaFuncAttributeMaxDynamicSharedMemorySize, GEMM_SMEM);
    cudaFuncSetAttribute(ctx, cudaFuncAttributeMaxDynamicSharedMemorySize, CTX_SMEM);

    split_hs<<<2048, 256>>>(hs);
    split_w<<<dim3(16, 16, 2), dim3(32, 8)>>>(Wq, Wk);
    gemm3<<<dim3(32, 4, 2), 256, GEMM_SMEM>>>();
    wts<<<dim3(SS, BB), 256>>>();
    ctx<<<dim3(64, 2, 2), 256, CTX_SMEM>>>(hs, out);
}

// round 6
// speedup vs baseline: 1.4391x; 1.4391x over previous
#include <cuda_runtime.h>
#include <cuda_bf16.h>
#include <cstdint>

#define BB 2
#define SS 2048
#define DD 512
#define HH 8
#define LR 7
#define MTOT (BB*SS)        // 4096
#define K3 (3*DD)           // 1536

// scratch
__device__ float g_q[MTOT * DD];
__device__ float g_k[MTOT * DD];
__device__ float g_w[MTOT * 128];           // [b*S+i][h*16+jj] normalized band weights
__device__ __nv_bfloat16 g_a3[MTOT * K3];   // [hi | lo | hi] along K
__device__ __nv_bfloat16 g_b3q[DD * K3];    // [hi | hi | lo] along K, rows = n
__device__ __nv_bfloat16 g_b3k[DD * K3];

#define SWZ128(off) ((off) ^ (((off) >> 3) & 0x70))

__device__ __forceinline__ uint32_t smem_u32(const void* p) {
    uint32_t a;
    asm("{ .reg .u64 t; cvta.to.shared.u64 t, %1; cvt.u32.u64 %0, t; }" : "=r"(a) : "l"(p));
    return a;
}
__device__ __forceinline__ void cp16(uint32_t s, const void* g) {
    asm volatile("cp.async.cg.shared.global [%0], [%1], 16;" :: "r"(s), "l"(g));
}
#define CP_COMMIT() asm volatile("cp.async.commit_group;" ::: "memory")

__device__ __forceinline__ void ldm_x4(uint32_t& r0, uint32_t& r1, uint32_t& r2, uint32_t& r3, uint32_t a) {
    asm volatile("ldmatrix.sync.aligned.m8n8.x4.shared.b16 {%0,%1,%2,%3}, [%4];"
                 : "=r"(r0), "=r"(r1), "=r"(r2), "=r"(r3) : "r"(a));
}
__device__ __forceinline__ void ldm_x2(uint32_t& r0, uint32_t& r1, uint32_t a) {
    asm volatile("ldmatrix.sync.aligned.m8n8.x2.shared.b16 {%0,%1}, [%2];"
                 : "=r"(r0), "=r"(r1) : "r"(a));
}
__device__ __forceinline__ void mma16816(float* d, const uint32_t* a, const uint32_t* b) {
    asm volatile("mma.sync.aligned.m16n8k16.row.col.f32.bf16.bf16.f32 "
                 "{%0,%1,%2,%3}, {%4,%5,%6,%7}, {%8,%9}, {%0,%1,%2,%3};"
                 : "+f"(d[0]), "+f"(d[1]), "+f"(d[2]), "+f"(d[3])
                 : "r"(a[0]), "r"(a[1]), "r"(a[2]), "r"(a[3]), "r"(b[0]), "r"(b[1]));
}

// ---------------------------------------------------------------------------
// split hidden_states into bf16 hi/lo, tripled K layout [hi|lo|hi]
// ---------------------------------------------------------------------------
__global__ void split_hs(const float* __restrict__ hs) {
    int idx = blockIdx.x * 256 + threadIdx.x;     // float4 index
    int m = idx >> 7;
    int c = idx & 127;
    float4 v = ((const float4*)hs)[idx];
    __nv_bfloat16 hx = __float2bfloat16(v.x), hy = __float2bfloat16(v.y);
    __nv_bfloat16 hz = __float2bfloat16(v.z), hw = __float2bfloat16(v.w);
    __nv_bfloat16 lx = __float2bfloat16(v.x - __bfloat162float(hx));
    __nv_bfloat16 ly = __float2bfloat16(v.y - __bfloat162float(hy));
    __nv_bfloat16 lz = __float2bfloat16(v.z - __bfloat162float(hz));
    __nv_bfloat16 lw = __float2bfloat16(v.w - __bfloat162float(hw));
    __nv_bfloat162 H0; H0.x = hx; H0.y = hy;
    __nv_bfloat162 H1; H1.x = hz; H1.y = hw;
    __nv_bfloat162 L0; L0.x = lx; L0.y = ly;
    __nv_bfloat162 L1; L1.x = lz; L1.y = lw;
    __nv_bfloat16* p = g_a3 + (size_t)m * K3 + 4 * c;
    *(__nv_bfloat162*)(p)          = H0; *(__nv_bfloat162*)(p + 2)          = H1;
    *(__nv_bfloat162*)(p + DD)     = L0; *(__nv_bfloat162*)(p + DD + 2)     = L1;
    *(__nv_bfloat162*)(p + 2*DD)   = H0; *(__nv_bfloat162*)(p + 2*DD + 2)   = H1;
}

// ---------------------------------------------------------------------------
// split + transpose W (stored [k, n]) into B3 [n, 3K] = [hi|hi|lo]
// ---------------------------------------------------------------------------
__global__ void split_w(const float* __restrict__ Wq, const float* __restrict__ Wk) {
    __shared__ float t[32][33];
    const float* W = blockIdx.z ? Wk : Wq;
    __nv_bfloat16* B3 = blockIdx.z ? g_b3k : g_b3q;
    int n0 = blockIdx.x * 32, k0 = blockIdx.y * 32;
    int tx = threadIdx.x, ty = threadIdx.y;           // (32, 8)
#pragma unroll
    for (int r = 0; r < 4; r++)
        t[ty + r * 8][tx] = W[(size_t)(k0 + ty + r * 8) * DD + n0 + tx];
    __syncthreads();
#pragma unroll
    for (int r = 0; r < 4; r++) {
        int n = n0 + ty + r * 8, k = k0 + tx;
        float v = t[tx][ty + r * 8];
        __nv_bfloat16 h = __float2bfloat16(v);
        __nv_bfloat16 l = __float2bfloat16(v - __bfloat162float(h));
        B3[(size_t)n * K3 + k]        = h;
        B3[(size_t)n * K3 + DD + k]   = h;
        B3[(size_t)n * K3 + 2*DD + k] = l;
    }
}

// ---------------------------------------------------------------------------
// mma.sync bf16 GEMM: C[4096,512] = A3[4096,1536] * B3[512,1536]^T, f32 acc
// ---------------------------------------------------------------------------
#define MT 128
#define NT 128
#define KT 64
#define NK 24          // 1536/64
#define STG 32768u     // 16KB A + 16KB B
#define NSTG 3
#define GEMM_SMEM (NSTG * STG)

__device__ __forceinline__ void load_tile(int tile, int stg,
                                          const char* Ab, const char* Bb,
                                          uint32_t sb, int tid) {
    size_t koff = (size_t)tile * (KT * 2);
    uint32_t sA = sb + (uint32_t)stg * STG;
    uint32_t sB = sA + 16384u;
#pragma unroll
    for (int c = 0; c < 4; c++) {
        int q = tid + c * 256;
        int r = q >> 3, col = (q & 7) * 16;
        cp16(sA + SWZ128(r * 128 + col), Ab + (size_t)r * (K3 * 2) + koff + col);
    }
#pragma unroll
    for (int c = 0; c < 4; c++) {
        int q = tid + c * 256;
        int r = q >> 3, col = (q & 7) * 16;
        cp16(sB + SWZ128(r * 128 + col), Bb + (size_t)r * (K3 * 2) + koff + col);
    }
}

__global__ __launch_bounds__(256, 2)
void gemm3() {
    extern __shared__ char smem[];
    uint32_t sb = smem_u32(smem);
    const int tid = threadIdx.x, wid = tid >> 5, lane = tid & 31;
    const int m0 = blockIdx.x * MT;
    const int n0 = blockIdx.y * NT;
    const __nv_bfloat16* B3 = blockIdx.z ? g_b3k : g_b3q;
    float* C = blockIdx.z ? g_k : g_q;

    const char* Ab = (const char*)g_a3 + (size_t)m0 * (K3 * 2);
    const char* Bb = (const char*)B3 + (size_t)n0 * (K3 * 2);

    const int wm = wid & 1;
    const int wn = wid >> 1;

    float acc[4][4][4];
#pragma unroll
    for (int i = 0; i < 4; i++)
#pragma unroll
        for (int j = 0; j < 4; j++)
#pragma unroll
            for (int r = 0; r < 4; r++) acc[i][j][r] = 0.f;

    load_tile(0, 0, Ab, Bb, sb, tid); CP_COMMIT();
    load_tile(1, 1, Ab, Bb, sb, tid); CP_COMMIT();

    const int a_row = wm * 64 + (lane & 15);
    const int a_cg  = (lane >> 4) * 16;
    const int b_row = wn * 32 + (lane & 7);
    const int b_cg  = ((lane >> 3) & 1) * 16;

    for (int t = 0; t < NK; t++) {
        asm volatile("cp.async.wait_group 1;" ::: "memory");
        __syncthreads();

        if (t + 2 < NK)
            load_tile(t + 2, (t + 2) % NSTG, Ab, Bb, sb, tid);
        CP_COMMIT();

        uint32_t sA = sb + (uint32_t)(t % NSTG) * STG;
        uint32_t sB = sA + 16384u;
#pragma unroll
        for (int ks = 0; ks < 4; ks++) {
            uint32_t af[4][4], bf[4][2];
#pragma unroll
            for (int mi = 0; mi < 4; mi++)
                ldm_x4(af[mi][0], af[mi][1], af[mi][2], af[mi][3],
                       sA + SWZ128((a_row + mi * 16) * 128 + ks * 32 + a_cg));
#pragma unroll
            for (int ni = 0; ni < 4; ni++)
                ldm_x2(bf[ni][0], bf[ni][1],
                       sB + SWZ128((b_row + ni * 8) * 128 + ks * 32 + b_cg));
#pragma unroll
            for (int mi = 0; mi < 4; mi++)
#pragma unroll
                for (int ni = 0; ni < 4; ni++)
                    mma16816(acc[mi][ni], af[mi], bf[ni]);
        }
    }

    const int er = lane >> 2;
    const int ec = (lane & 3) * 2;
#pragma unroll
    for (int mi = 0; mi < 4; mi++) {
        int r0 = m0 + wm * 64 + mi * 16 + er;
#pragma unroll
        for (int ni = 0; ni < 4; ni++) {
            int cc = n0 + wn * 32 + ni * 8 + ec;
            *(float2*)(C + (size_t)r0 * DD + cc) = make_float2(acc[mi][ni][0], acc[mi][ni][1]);
            *(float2*)(C + (size_t)(r0 + 8) * DD + cc) = make_float2(acc[mi][ni][2], acc[mi][ni][3]);
        }
    }
}

// ---------------------------------------------------------------------------
// wts v2: warp per (b,i). Lane owns 16 contiguous floats -> head = lane/4.
// Per jj: 4 coalesced float4 k loads + FMA + 2-shuffle fold within 4-lane group.
// grid (256, 2), block 256 (8 warps = 8 consecutive i)
// ---------------------------------------------------------------------------
__global__ __launch_bounds__(256)
void wts() {
    const int b = blockIdx.y;
    const int wid = threadIdx.x >> 5, lane = threadIdx.x & 31;
    const int i = blockIdx.x * 8 + wid;
    const int h = lane >> 2;          // head this lane contributes to
    const int g = lane & 3;

    const float4* q4 = (const float4*)(g_q + ((size_t)b * SS + i) * DD) + lane * 4;
    float4 ql[4];
#pragma unroll
    for (int t = 0; t < 4; t++) ql[t] = q4[t];

    float sc[15];
#pragma unroll
    for (int jj = 0; jj < 15; jj++) {
        int j = i - LR + jj;
        bool valid = (j >= 0) && (j < SS);
        int jc = j < 0 ? 0 : (j >= SS ? SS - 1 : j);
        const float4* k4 = (const float4*)(g_k + ((size_t)b * SS + jc) * DD) + lane * 4;
        float p = 0.f;
#pragma unroll
        for (int t = 0; t < 4; t++) {
            float4 kv = k4[t];
            p += ql[t].x * kv.x + ql[t].y * kv.y + ql[t].z * kv.z + ql[t].w * kv.w;
        }
        p += __shfl_xor_sync(0xffffffffu, p, 1);
        p += __shfl_xor_sync(0xffffffffu, p, 2);   // all 4 lanes of head have full dot
        sc[jj] = valid ? p * 0.125f : -1e30f;
    }

    float m = -1e30f;
#pragma unroll
    for (int jj = 0; jj < 15; jj++) m = fmaxf(m, sc[jj]);
    float s = 0.f;
#pragma unroll
    for (int jj = 0; jj < 15; jj++) { sc[jj] = __expf(sc[jj] - m); s += sc[jj]; }
    float inv = 1.f / s;

    float* wp = g_w + (((size_t)b * SS + i) << 7) + h * 16;
#pragma unroll
    for (int jj = g; jj < 15; jj += 4)
        wp[jj] = sc[jj] * inv;
}

// ---------------------------------------------------------------------------
// ctx v2: out[b,h,i,:] = sum_jj w[b,i,h,jj] * hs[b, i-7+jj, :]
// grid (64, 2, 2) = (ic, dc, b); block 256; chunk 32 rows x 256 cols.
// All 8 heads accumulated in registers while v streams once per jj;
// weights are warp-uniform smem broadcasts.
// ---------------------------------------------------------------------------
#define CTX_SMEM ((46 * 256 + 32 * 128) * 4)

__global__ __launch_bounds__(256, 2)
void ctx(const float* __restrict__ hs, float* __restrict__ out) {
    extern __shared__ float sm[];
    float* sh = sm;                 // [46][256]
    float* sw = sm + 46 * 256;      // [32][128]

    const int ic = blockIdx.x, dc = blockIdx.y, b = blockIdx.z;
    const int i0 = ic * 32, d0 = dc * 256;
    const int tid = threadIdx.x;

    for (int idx = tid; idx < 46 * 64; idx += 256) {
        int r = idx >> 6, c = idx & 63;
        int j = i0 - LR + r;
        j = j < 0 ? 0 : (j >= SS ? SS - 1 : j);
        ((float4*)sh)[idx] = ((const float4*)(hs + ((size_t)b * SS + j) * DD + d0))[c];
    }
    {
        const float4* gw4 = (const float4*)(g_w + (((size_t)b * SS + i0) << 7));
        for (int idx = tid; idx < 1024; idx += 256)
            ((float4*)sw)[idx] = gw4[idx];
    }
    __syncthreads();

    const int wid = tid >> 5, lane = tid & 31;
    const float4* sh4 = (const float4*)sh;     // row stride 64 float4

#pragma unroll
    for (int ii = 0; ii < 4; ii++) {
        const int il = ii * 8 + wid;           // local row 0..31 (warp-uniform)
        const int ig = i0 + il;
        const float* wp = &sw[il * 128];
#pragma unroll
        for (int cp = 0; cp < 2; cp++) {
            const int c4 = lane + 32 * cp;
            float4 acc[HH];
#pragma unroll
            for (int h = 0; h < HH; h++) { acc[h].x = acc[h].y = acc[h].z = acc[h].w = 0.f; }
#pragma unroll
            for (int jj = 0; jj < 15; jj++) {
                float4 v = sh4[(il + jj) * 64 + c4];
#pragma unroll
                for (int h = 0; h < HH; h++) {
                    float wv = wp[h * 16 + jj];   // warp-uniform broadcast
                    acc[h].x += wv * v.x;
                    acc[h].y += wv * v.y;
                    acc[h].z += wv * v.z;
                    acc[h].w += wv * v.w;
                }
            }
#pragma unroll
            for (int h = 0; h < HH; h++)
                *(float4*)(out + (((size_t)b * HH + h) * SS + ig) * DD + d0 + c4 * 4) = acc[h];
        }
    }
}

// ---------------------------------------------------------------------------
extern "C" void kernel_launch(void* const* d_in, const int* in_sizes, int n_in,
                              void* d_out, int out_size) {
    const float* hs = (const float*)d_in[0];
    const float* Wq = (const float*)d_in[1];
    const float* Wk = (const float*)d_in[2];
    float* out = (float*)d_out;

    cudaFuncSetAttribute(gemm3, cudaFuncAttributeMaxDynamicSharedMemorySize, GEMM_SMEM);
    cudaFuncSetAttribute(ctx, cudaFuncAttributeMaxDynamicSharedMemorySize, CTX_SMEM);

    split_hs<<<2048, 256>>>(hs);
    split_w<<<dim3(16, 16, 2), dim3(32, 8)>>>(Wq, Wk);
    gemm3<<<dim3(32, 4, 2), 256, GEMM_SMEM>>>();
    wts<<<dim3(SS / 8, BB), 256>>>();
    ctx<<<dim3(64, 2, 2), 256, CTX_SMEM>>>(hs, out);
}